// round 1
// baseline (speedup 1.0000x reference)
#include <cuda_runtime.h>
#include <stdint.h>

#define T_ 1024
#define B_ 64
#define H_ 256
#define G3 768   // 3*H

// ---------------- scratch (static device globals; no runtime allocation) ----------------
__device__ float g_xg[(size_t)2 * T_ * G3 * B_];   // [dir][t][n=gate*H+j][b]  (~402 MB)
__device__ float g_y [(size_t)2 * T_ * H_ * B_];   // [dir][t][j][b]           (~128 MB)
__device__ float g_h [2 * 2 * H_ * B_];            // [dir][parity][k][b]
__device__ unsigned          g_arrive[2];
__device__ volatile unsigned g_phase[2];

// ---------------- init: zero h state + barrier state (must run every replay) ----------------
__global__ void __launch_bounds__(256) init_kernel() {
    int i = blockIdx.x * 256 + threadIdx.x;
    if (i < 2 * 2 * H_ * B_) g_h[i] = 0.f;
    if (i < 2) { g_arrive[i] = 0u; g_phase[i] = 0u; }
}

// ---------------- phase 1: xg = gather(emb) @ W_ih^T + b_ih, stored transposed [t][n][b] ----------------
// Tile: one t (64 b) x 128 n, BK=32. Output C^T so recurrence reads are coalesced.
__global__ void __launch_bounds__(256) gemm_xg(const int* __restrict__ seq,
                                               const float* __restrict__ emb,
                                               const float* __restrict__ Wf,
                                               const float* __restrict__ Wb,
                                               const float* __restrict__ bf,
                                               const float* __restrict__ bb) {
    int t  = blockIdx.x / 12;
    int nt = blockIdx.x % 12;
    int d  = nt / 6;
    int n_base = (nt % 6) * 128;
    const float* W    = d ? Wb : Wf;
    const float* bias = d ? bb : bf;

    __shared__ float eT[32][68];    // emb tile transposed [k][b], pad 68 (16B-aligned rows)
    __shared__ float wT[32][132];   // W tile transposed [k][n], pad 132
    __shared__ int   tok[64];

    int tid = threadIdx.x;
    if (tid < 64) tok[tid] = seq[t * 64 + tid];

    int ni = tid & 15, bi = tid >> 4;
    int n0 = ni * 8, b0 = bi * 4;
    float c[8][4];
#pragma unroll
    for (int i = 0; i < 8; i++)
#pragma unroll
        for (int j = 0; j < 4; j++) c[i][j] = 0.f;

    const float4* emb4 = reinterpret_cast<const float4*>(emb);
    const float4* W4   = reinterpret_cast<const float4*>(W);

    for (int k0 = 0; k0 < 256; k0 += 32) {
        __syncthreads();
        // embedding tile (gathered rows), transposed into eT
#pragma unroll
        for (int l = 0; l < 2; l++) {
            int fid = tid + l * 256;
            int b = fid >> 3, kq = fid & 7;
            float4 v = emb4[(size_t)tok[b] * 64 + (k0 >> 2) + kq];
            eT[kq * 4 + 0][b] = v.x; eT[kq * 4 + 1][b] = v.y;
            eT[kq * 4 + 2][b] = v.z; eT[kq * 4 + 3][b] = v.w;
        }
        // W tile, transposed into wT
#pragma unroll
        for (int l = 0; l < 4; l++) {
            int fid = tid + l * 256;
            int n = fid >> 3, kq = fid & 7;
            float4 v = W4[(size_t)(n_base + n) * 64 + (k0 >> 2) + kq];
            wT[kq * 4 + 0][n] = v.x; wT[kq * 4 + 1][n] = v.y;
            wT[kq * 4 + 2][n] = v.z; wT[kq * 4 + 3][n] = v.w;
        }
        __syncthreads();
#pragma unroll
        for (int kk = 0; kk < 32; kk++) {
            float4 hb = *reinterpret_cast<const float4*>(&eT[kk][b0]);
            float4 w0 = *reinterpret_cast<const float4*>(&wT[kk][n0]);
            float4 w1 = *reinterpret_cast<const float4*>(&wT[kk][n0 + 4]);
            float wv[8] = {w0.x, w0.y, w0.z, w0.w, w1.x, w1.y, w1.z, w1.w};
            float hv[4] = {hb.x, hb.y, hb.z, hb.w};
#pragma unroll
            for (int i = 0; i < 8; i++)
#pragma unroll
                for (int j = 0; j < 4; j++) c[i][j] += wv[i] * hv[j];
        }
    }

    float* out = &g_xg[(size_t)d * T_ * G3 * B_ + (size_t)t * G3 * B_];
#pragma unroll
    for (int i = 0; i < 8; i++) {
        int n = n_base + n0 + i;
        float bv = bias[n];
        float4 v;
        v.x = c[i][0] + bv; v.y = c[i][1] + bv;
        v.z = c[i][2] + bv; v.w = c[i][3] + bv;
        *reinterpret_cast<float4*>(&out[(size_t)n * 64 + b0]) = v;
    }
}

// ---------------- phase 2: persistent bidirectional GRU recurrence ----------------
// grid = 128 CTAs: dir = blk/64 (forward/backward), each CTA owns 4 hidden units.
// 128 threads: thread = (g in 0..1) * 64 + b ; handles j = jb+2g, jb+2g+1 for batch b.
__global__ void __launch_bounds__(128) recur_kernel(const float* __restrict__ Whh_f,
                                                    const float* __restrict__ Whh_b,
                                                    const float* __restrict__ bhh_f,
                                                    const float* __restrict__ bhh_b,
                                                    const int* __restrict__ lengths) {
    extern __shared__ float sm[];
    float*  h_s = sm;                                   // [256][64]  64 KB
    float4* wT  = reinterpret_cast<float4*>(sm + H_ * B_);  // [256][4] : (r,z,n,pad) per j_local, 16 KB

    int d   = blockIdx.x >> 6;
    int cid = blockIdx.x & 63;
    int jb  = cid * 4;
    const float* Whh = d ? Whh_b : Whh_f;
    const float* bhh = d ? bhh_b : bhh_f;

    int tid = threadIdx.x;
    int g = tid >> 6, b = tid & 63;
    int j0 = jb + 2 * g;

    // load transposed weight slice: wT[k][jl] = (Whh[r], Whh[z], Whh[n], 0)
    for (int idx = tid; idx < 256 * 16; idx += 128) {
        int k = idx >> 4, r = idx & 15, jl = r >> 2, gate = r & 3;
        float v = 0.f;
        if (gate < 3) v = Whh[(size_t)(gate * 256 + jb + jl) * 256 + k];
        reinterpret_cast<float*>(wT)[idx] = v;
    }
    float bias[2][3];
#pragma unroll
    for (int jj = 0; jj < 2; jj++)
#pragma unroll
        for (int gate = 0; gate < 3; gate++)
            bias[jj][gate] = bhh[gate * 256 + j0 + jj];
    int len_b = lengths[b];

    float* yout = &g_y[(size_t)d * T_ * H_ * B_];
    const float* xgbase = &g_xg[(size_t)d * T_ * G3 * B_];
    __syncthreads();

    for (int step = 0; step < T_; step++) {
        int t = d ? (T_ - 1 - step) : step;
        int p = step & 1;
        const float4* hin4 = reinterpret_cast<const float4*>(&g_h[(d * 2 + p) * H_ * B_]);
        float*        hout = &g_h[(d * 2 + (p ^ 1)) * H_ * B_];

        // stage h (written by peer CTAs last step) into smem; .cg: bypass (stale) L1
        float4* hs4 = reinterpret_cast<float4*>(h_s);
#pragma unroll 8
        for (int i = tid; i < 4096; i += 128) hs4[i] = __ldcg(&hin4[i]);

        const float* xg = &xgbase[(size_t)t * G3 * B_];
        float xr0 = xg[(size_t)(0 * 256 + j0 + 0) * 64 + b];
        float xz0 = xg[(size_t)(1 * 256 + j0 + 0) * 64 + b];
        float xn0 = xg[(size_t)(2 * 256 + j0 + 0) * 64 + b];
        float xr1 = xg[(size_t)(0 * 256 + j0 + 1) * 64 + b];
        float xz1 = xg[(size_t)(1 * 256 + j0 + 1) * 64 + b];
        float xn1 = xg[(size_t)(2 * 256 + j0 + 1) * 64 + b];
        __syncthreads();

        float a00 = bias[0][0], a01 = bias[0][1], a02 = bias[0][2];
        float a10 = bias[1][0], a11 = bias[1][1], a12 = bias[1][2];
#pragma unroll 8
        for (int k = 0; k < 256; k++) {
            float  hk = h_s[k * 64 + b];
            float4 w0 = wT[k * 4 + 2 * g];
            float4 w1 = wT[k * 4 + 2 * g + 1];
            a00 += hk * w0.x; a01 += hk * w0.y; a02 += hk * w0.z;
            a10 += hk * w1.x; a11 += hk * w1.y; a12 += hk * w1.z;
        }

        bool m = (t < len_b);
#pragma unroll
        for (int jj = 0; jj < 2; jj++) {
            float ar = jj ? a10 : a00, az = jj ? a11 : a01, an = jj ? a12 : a02;
            float xr = jj ? xr1 : xr0, xz = jj ? xz1 : xz0, xn = jj ? xn1 : xn0;
            int   j  = j0 + jj;
            float hprev = h_s[j * 64 + b];
            float r  = 1.f / (1.f + __expf(-(xr + ar)));
            float z  = 1.f / (1.f + __expf(-(xz + az)));
            float nn = 2.f / (1.f + __expf(-2.f * (xn + r * an))) - 1.f;
            float hn = nn + z * (hprev - nn);
            float hnext = m ? hn : hprev;
            float y     = m ? hn : 0.f;
            __stcg(&hout[j * 64 + b], hnext);
            yout[((size_t)t * H_ + j) * 64 + b] = y;
        }

        // grid-wide (per-direction) barrier: monotonic arrive counter + phase publish
        __threadfence();
        __syncthreads();
        if (tid == 0) {
            unsigned target = 64u * (unsigned)(step + 1);
            unsigned old = atomicAdd(&g_arrive[d], 1u);
            if (old == target - 1u) {
                __threadfence();
                g_phase[d] = (unsigned)(step + 1);
            } else {
                while (g_phase[d] < (unsigned)(step + 1)) __nanosleep(64);
            }
            __threadfence();
        }
        __syncthreads();
    }
}

// ---------------- phase 3: outputs = yf + yb (transpose to [t][b][j]) + hidden ----------------
__global__ void __launch_bounds__(256) epilogue_kernel(float* __restrict__ out) {
    __shared__ float s[128][65];
    int t = blockIdx.x;
    if (t < T_) {
        const float* yf = &g_y[(size_t)0 * T_ * H_ * B_ + (size_t)t * H_ * B_];
        const float* yb = &g_y[(size_t)1 * T_ * H_ * B_ + (size_t)t * H_ * B_];
        for (int half = 0; half < 2; half++) {
            int jofs = half * 128;
            for (int idx = threadIdx.x; idx < 128 * 64; idx += 256) {
                int j = idx >> 6, b = idx & 63;
                size_t o = (size_t)(jofs + j) * 64 + b;
                s[j][b] = yf[o] + yb[o];
            }
            __syncthreads();
            for (int idx = threadIdx.x; idx < 128 * 64; idx += 256) {
                int b = idx >> 7, j = idx & 127;
                out[((size_t)t * 64 + b) * 256 + jofs + j] = s[j][b];
            }
            __syncthreads();
        }
    } else {
        // hidden = final h per direction (parity 0 after 1024 steps), transpose [k][b]->[b][k]
        for (int d = 0; d < 2; d++) {
            const float* hf = &g_h[(d * 2 + 0) * H_ * B_];
            for (int idx = threadIdx.x; idx < H_ * B_; idx += 256) {
                int k = idx >> 6, b = idx & 63;
                out[(size_t)T_ * B_ * H_ + (size_t)d * B_ * H_ + (size_t)b * H_ + k] = hf[k * 64 + b];
            }
        }
    }
}

// ---------------- launcher ----------------
extern "C" void kernel_launch(void* const* d_in, const int* in_sizes, int n_in,
                              void* d_out, int out_size) {
    const int*   seq  = (const int*)  d_in[0];
    const int*   lens = (const int*)  d_in[1];
    const float* emb  = (const float*)d_in[2];
    const float* Wihf = (const float*)d_in[3];
    const float* Whhf = (const float*)d_in[4];
    const float* bihf = (const float*)d_in[5];
    const float* bhhf = (const float*)d_in[6];
    const float* Wihb = (const float*)d_in[7];
    const float* Whhb = (const float*)d_in[8];
    const float* bihb = (const float*)d_in[9];
    const float* bhhb = (const float*)d_in[10];
    float* out = (float*)d_out;

    const int smem_recur = H_ * B_ * 4 + 256 * 4 * 16;   // 64KB h + 16KB weights = 80KB
    cudaFuncSetAttribute(recur_kernel, cudaFuncAttributeMaxDynamicSharedMemorySize, smem_recur);

    init_kernel<<<256, 256>>>();
    gemm_xg<<<T_ * 12, 256>>>(seq, emb, Wihf, Wihb, bihf, bihb);
    recur_kernel<<<128, 128, smem_recur>>>(Whhf, Whhb, bhhf, bhhb, lens);
    epilogue_kernel<<<T_ + 1, 256>>>(out);
}

// round 2
// speedup vs baseline: 1.4291x; 1.4291x over previous
#include <cuda_runtime.h>
#include <stdint.h>

#define T_ 1024
#define B_ 64
#define H_ 256
#define G3 768   // 3*H

typedef unsigned long long ull;

// ---------------- scratch (static device globals; no runtime allocation) ----------------
__device__ float g_xg[(size_t)2 * T_ * G3 * B_];   // [dir][t][n=gate*H+j][b]  (~402 MB)
__device__ float g_y [(size_t)2 * T_ * H_ * B_];   // [dir][t][j][b]           (~128 MB)
__device__ float g_h [2 * 2 * 4 * H_ * 16];        // [dir][parity][bg][k][16]  (256 KB)
__device__ unsigned          g_arrive[2];
__device__ volatile unsigned g_phase[2];

// f32x2 packed math helpers
__device__ __forceinline__ void fma2(ull& acc, ull a, ull b) {
    asm("fma.rn.f32x2 %0, %1, %2, %0;" : "+l"(acc) : "l"(a), "l"(b));
}
__device__ __forceinline__ ull add2(ull a, ull b) {
    ull r; asm("add.rn.f32x2 %0, %1, %2;" : "=l"(r) : "l"(a), "l"(b)); return r;
}
__device__ __forceinline__ ull packdup(float v) {
    unsigned u = __float_as_uint(v);
    return ((ull)u << 32) | u;
}
__device__ __forceinline__ float2 u2f(ull v) {
    float2 f;
    f.x = __uint_as_float((unsigned)v);
    f.y = __uint_as_float((unsigned)(v >> 32));
    return f;
}

// ---------------- init: zero h state + barrier state (must run every replay) ----------------
__global__ void __launch_bounds__(256) init_kernel() {
    int i = blockIdx.x * 256 + threadIdx.x;
    if (i < 2 * 2 * 4 * H_ * 16) g_h[i] = 0.f;
    if (i < 2) { g_arrive[i] = 0u; g_phase[i] = 0u; }
}

// ---------------- phase 1: xg = gather(emb) @ W_ih^T + b_ih, stored transposed [t][n][b] --
// Block: one t, 128 n, 32 b (btile).  Skips tiles where all batches are masked.
// f32x2 packed FFMA with pre-duplicated weights in smem.
__global__ void __launch_bounds__(256) gemm_xg(const int* __restrict__ seq,
                                               const float* __restrict__ emb,
                                               const float* __restrict__ Wf,
                                               const float* __restrict__ Wb,
                                               const float* __restrict__ bf,
                                               const float* __restrict__ bb,
                                               const int* __restrict__ lengths) {
    int id = blockIdx.x;
    int t   = id / 24;
    int r   = id % 24;
    int bt  = r & 1;               // b half-tile (0: b 0..31, 1: b 32..63)
    int nt2 = r >> 1;              // 0..11
    int d   = nt2 / 6;
    int n_base = (nt2 % 6) * 128;

    // skip fully-masked b-tiles (lengths sorted descending -> max len at tile's first b)
    if (t >= __ldg(&lengths[bt * 32])) return;

    const float* W    = d ? Wb : Wf;
    const float* bias = d ? bb : bf;

    __shared__ float  eT[32][40];        // emb tile transposed [k][b], padded (160B rows)
    __shared__ float2 wd2[32 * 128];     // duplicated W tile [k][n] = (w,w)
    __shared__ int    tok[32];

    int tid = threadIdx.x;
    if (tid < 32) tok[tid] = seq[t * 64 + bt * 32 + tid];

    int nq = tid >> 3, bq = tid & 7;     // 32 x 8
    int n0 = nq * 4, b0 = bq * 4;

    ull acc[4][2];
#pragma unroll
    for (int i = 0; i < 4; i++) { acc[i][0] = 0ull; acc[i][1] = 0ull; }

    const float4* emb4 = reinterpret_cast<const float4*>(emb);
    const float4* W4   = reinterpret_cast<const float4*>(W);

    for (int k0 = 0; k0 < 256; k0 += 32) {
        __syncthreads();
        // embedding tile (gathered rows), transposed into eT
        {
            int b = tid >> 3, kq = tid & 7;
            float4 v = emb4[(size_t)tok[b] * 64 + (k0 >> 2) + kq];
            eT[kq * 4 + 0][b] = v.x; eT[kq * 4 + 1][b] = v.y;
            eT[kq * 4 + 2][b] = v.z; eT[kq * 4 + 3][b] = v.w;
        }
        // W tile, duplicated pairs into wd2
#pragma unroll
        for (int l = 0; l < 4; l++) {
            int fid = tid + l * 256;
            int n = fid >> 3, kq = fid & 7;
            float4 v = W4[(size_t)(n_base + n) * 64 + (k0 >> 2) + kq];
            wd2[(kq * 4 + 0) * 128 + n] = make_float2(v.x, v.x);
            wd2[(kq * 4 + 1) * 128 + n] = make_float2(v.y, v.y);
            wd2[(kq * 4 + 2) * 128 + n] = make_float2(v.z, v.z);
            wd2[(kq * 4 + 3) * 128 + n] = make_float2(v.w, v.w);
        }
        __syncthreads();
#pragma unroll 8
        for (int kk = 0; kk < 32; kk++) {
            ulonglong2 hh = *reinterpret_cast<const ulonglong2*>(&eT[kk][b0]);
            ulonglong2 w01 = *reinterpret_cast<const ulonglong2*>(&wd2[kk * 128 + n0]);
            ulonglong2 w23 = *reinterpret_cast<const ulonglong2*>(&wd2[kk * 128 + n0 + 2]);
            fma2(acc[0][0], hh.x, w01.x); fma2(acc[0][1], hh.y, w01.x);
            fma2(acc[1][0], hh.x, w01.y); fma2(acc[1][1], hh.y, w01.y);
            fma2(acc[2][0], hh.x, w23.x); fma2(acc[2][1], hh.y, w23.x);
            fma2(acc[3][0], hh.x, w23.y); fma2(acc[3][1], hh.y, w23.y);
        }
    }

    float* out = &g_xg[(size_t)d * T_ * G3 * B_ + (size_t)t * G3 * B_];
#pragma unroll
    for (int i = 0; i < 4; i++) {
        int n = n_base + n0 + i;
        float bv = bias[n];
        float2 lo = u2f(acc[i][0]), hi = u2f(acc[i][1]);
        float4 v;
        v.x = lo.x + bv; v.y = lo.y + bv; v.z = hi.x + bv; v.w = hi.y + bv;
        *reinterpret_cast<float4*>(&out[(size_t)n * 64 + bt * 32 + b0]) = v;
    }
}

// ---------------- phase 2: persistent bidirectional GRU recurrence ----------------
// grid = 128 CTAs: dir = blk>>6; within dir: 16 j-groups (16 j each) x 4 b-groups (16 b each).
// 256 threads = kh(2) x jl(16) x bp(8): k-split halves with smem reduction,
// each (jl,bp) handles hidden j and batch pair (2b) with f32x2 accumulators.
__global__ void __launch_bounds__(256) recur_kernel(const float* __restrict__ Whh_f,
                                                    const float* __restrict__ Whh_b,
                                                    const float* __restrict__ bhh_f,
                                                    const float* __restrict__ bhh_b,
                                                    const int* __restrict__ lengths) {
    extern __shared__ char smraw[];
    float* h_s  = reinterpret_cast<float*>(smraw);                    // [256][16]  16 KB
    ull*   wdup = reinterpret_cast<ull*>(smraw + 16384);              // [256][16][4] 128 KB
    ull*   spart = reinterpret_cast<ull*>(smraw + 16384 + 131072);    // [128][3]     3 KB

    int d   = blockIdx.x >> 6;
    int cid = blockIdx.x & 63;
    int jg  = cid >> 2;          // 0..15
    int bg  = cid & 3;           // 0..3
    const float* Whh = d ? Whh_b : Whh_f;
    const float* bhh = d ? bhh_b : bhh_f;

    int tid = threadIdx.x;
    int kh = tid >> 7;           // k half
    int rr = tid & 127;
    int jl = rr >> 3;            // 0..15
    int bp = rr & 7;             // 0..7 (batch pair)
    int j  = jg * 16 + jl;       // global hidden index this thread produces
    int b0 = bg * 16 + bp * 2;   // global batch of pair element 0

    // load weights: wdup[k][jl][gate] = (Whh[gate*256+j, k], same)  pre-duplicated
    for (int idx = tid; idx < 256 * 48; idx += 256) {
        int k = idx / 48;
        int rem = idx - k * 48;
        int jl2 = rem / 3;
        int g = rem - jl2 * 3;
        float v = Whh[(size_t)(g * 256 + jg * 16 + jl2) * 256 + k];
        wdup[(k * 16 + jl2) * 4 + g] = packdup(v);
    }

    float br = bhh[0 * 256 + j];
    float bz = bhh[1 * 256 + j];
    float bn = bhh[2 * 256 + j];
    int len0 = lengths[b0];
    int len1 = lengths[b0 + 1];

    float* yout = &g_y[(size_t)d * T_ * H_ * B_];
    const float* xgbase = &g_xg[(size_t)d * T_ * G3 * B_];
    const int kbase = kh * 128;
    __syncthreads();

    for (int step = 0; step < T_; step++) {
        int t = d ? (T_ - 1 - step) : step;
        int p = step & 1;
        // h slice for my b-group: contiguous 16KB
        const float4* hin4 = reinterpret_cast<const float4*>(
            &g_h[((d * 2 + p) * 4 + bg) * (H_ * 16)]);
        float* hout = &g_h[((d * 2 + (p ^ 1)) * 4 + bg) * (H_ * 16)];

        // stage h (written by peer CTAs last step); .cg mandatory (L1 not coherent)
        float4* hs4 = reinterpret_cast<float4*>(h_s);
#pragma unroll
        for (int i = 0; i < 4; i++) hs4[tid + i * 256] = __ldcg(&hin4[tid + i * 256]);

        // prefetch xg for this step (kh==0 threads only use it)
        const float* xg = &xgbase[(size_t)t * G3 * B_];
        float2 xr = *reinterpret_cast<const float2*>(&xg[(size_t)(0 * 256 + j) * 64 + b0]);
        float2 xz = *reinterpret_cast<const float2*>(&xg[(size_t)(1 * 256 + j) * 64 + b0]);
        float2 xn = *reinterpret_cast<const float2*>(&xg[(size_t)(2 * 256 + j) * 64 + b0]);
        __syncthreads();

        // half-k dot products, f32x2 over the batch pair
        ull ar = 0ull, az = 0ull, an = 0ull;
#pragma unroll 8
        for (int k = 0; k < 128; k++) {
            int kk = kbase + k;
            ull h2 = *reinterpret_cast<const ull*>(&h_s[kk * 16 + bp * 2]);
            const ulonglong2* w2 = reinterpret_cast<const ulonglong2*>(&wdup[(kk * 16 + jl) * 4]);
            ulonglong2 wrz = *w2;
            ull wn = reinterpret_cast<const ull*>(w2)[2];
            fma2(ar, h2, wrz.x);
            fma2(az, h2, wrz.y);
            fma2(an, h2, wn);
        }

        if (kh) {
            spart[rr * 3 + 0] = ar;
            spart[rr * 3 + 1] = az;
            spart[rr * 3 + 2] = an;
        }
        __syncthreads();

        if (!kh) {
            ar = add2(ar, spart[rr * 3 + 0]);
            az = add2(az, spart[rr * 3 + 1]);
            an = add2(an, spart[rr * 3 + 2]);
            float2 fr = u2f(ar), fz = u2f(az), fn = u2f(an);
            float2 hprev = *reinterpret_cast<const float2*>(&h_s[j * 16 + bp * 2]);

            float hnext[2], yv[2];
#pragma unroll
            for (int e = 0; e < 2; e++) {
                float accr = e ? fr.y : fr.x, accz = e ? fz.y : fz.x, accn = e ? fn.y : fn.x;
                float xrv = e ? xr.y : xr.x, xzv = e ? xz.y : xz.x, xnv = e ? xn.y : xn.x;
                float hp = e ? hprev.y : hprev.x;
                float rg = 1.f / (1.f + __expf(-(xrv + accr + br)));
                float zg = 1.f / (1.f + __expf(-(xzv + accz + bz)));
                float ng = 2.f / (1.f + __expf(-2.f * (xnv + rg * (accn + bn)))) - 1.f;
                float hn = ng + zg * (hp - ng);
                bool m = (t < (e ? len1 : len0));
                hnext[e] = m ? hn : hp;
                yv[e]    = m ? hn : 0.f;
            }
            __stcg(reinterpret_cast<float2*>(&hout[j * 16 + bp * 2]),
                   make_float2(hnext[0], hnext[1]));
            *reinterpret_cast<float2*>(&yout[((size_t)t * H_ + j) * 64 + b0]) =
                make_float2(yv[0], yv[1]);
        }

        // grid-wide (per-direction) barrier
        __threadfence();
        __syncthreads();
        if (tid == 0) {
            unsigned target = 64u * (unsigned)(step + 1);
            unsigned old = atomicAdd(&g_arrive[d], 1u);
            if (old == target - 1u) {
                __threadfence();
                g_phase[d] = (unsigned)(step + 1);
            } else {
                while (g_phase[d] < (unsigned)(step + 1)) __nanosleep(32);
            }
            __threadfence();
        }
        __syncthreads();
    }
}

// ---------------- phase 3: outputs = yf + yb (transpose to [t][b][j]) + hidden ----------------
__global__ void __launch_bounds__(256) epilogue_kernel(float* __restrict__ out) {
    __shared__ float s[128][65];
    int t = blockIdx.x;
    if (t < T_) {
        const float* yf = &g_y[(size_t)0 * T_ * H_ * B_ + (size_t)t * H_ * B_];
        const float* yb = &g_y[(size_t)1 * T_ * H_ * B_ + (size_t)t * H_ * B_];
        for (int half = 0; half < 2; half++) {
            int jofs = half * 128;
            for (int idx = threadIdx.x; idx < 128 * 64; idx += 256) {
                int j = idx >> 6, b = idx & 63;
                size_t o = (size_t)(jofs + j) * 64 + b;
                s[j][b] = yf[o] + yb[o];
            }
            __syncthreads();
            for (int idx = threadIdx.x; idx < 128 * 64; idx += 256) {
                int b = idx >> 7, j = idx & 127;
                out[((size_t)t * 64 + b) * 256 + jofs + j] = s[j][b];
            }
            __syncthreads();
        }
    } else {
        // hidden: g_h[dir][parity 0][bg][k][16] -> out[T*B*H + d*B*H + b*H + k]
        for (int idx = threadIdx.x; idx < 2 * H_ * B_; idx += 256) {
            int d = idx >> 14;
            int rem = idx & 16383;
            int k = rem >> 6, b = rem & 63;
            float v = g_h[((d * 2 + 0) * 4 + (b >> 4)) * (H_ * 16) + k * 16 + (b & 15)];
            out[(size_t)T_ * B_ * H_ + (size_t)d * B_ * H_ + (size_t)b * H_ + k] = v;
        }
    }
}

// ---------------- launcher ----------------
extern "C" void kernel_launch(void* const* d_in, const int* in_sizes, int n_in,
                              void* d_out, int out_size) {
    const int*   seq  = (const int*)  d_in[0];
    const int*   lens = (const int*)  d_in[1];
    const float* emb  = (const float*)d_in[2];
    const float* Wihf = (const float*)d_in[3];
    const float* Whhf = (const float*)d_in[4];
    const float* bihf = (const float*)d_in[5];
    const float* bhhf = (const float*)d_in[6];
    const float* Wihb = (const float*)d_in[7];
    const float* Whhb = (const float*)d_in[8];
    const float* bihb = (const float*)d_in[9];
    const float* bhhb = (const float*)d_in[10];
    float* out = (float*)d_out;

    const int smem_recur = 16384 + 131072 + 3072;   // h 16K + wdup 128K + partials 3K
    cudaFuncSetAttribute(recur_kernel, cudaFuncAttributeMaxDynamicSharedMemorySize, smem_recur);

    init_kernel<<<256, 256>>>();
    gemm_xg<<<T_ * 24, 256>>>(seq, emb, Wihf, Wihb, bihf, bihb, lens);
    recur_kernel<<<128, 256, smem_recur>>>(Whhf, Whhb, bhhf, bhhb, lens);
    epilogue_kernel<<<T_ + 1, 256>>>(out);
}